// round 15
// baseline (speedup 1.0000x reference)
#include <cuda_runtime.h>
#include <cuda_fp16.h>
#include <cstdint>

#define HEADS 16
#define HID   1024
#define DH    64
#define BATCH 2
#define SEQ   2048
#define MROWS (BATCH*SEQ)
#define KDIM  1024

// ---------------- scratch (__device__ globals; alloc-free rule) -------------
__device__ __half g_Q[(size_t)BATCH*HEADS*SEQ*DH];   // pre-scaled by SCALE*log2e
__device__ __half g_K[(size_t)BATCH*HEADS*SEQ*DH];   // compact-domain rows
__device__ __half g_V[(size_t)BATCH*HEADS*SEQ*DH];   // compact-domain rows

__device__ __half g_X [(size_t)MROWS*HID];
__device__ __half g_O [(size_t)MROWS*HID];
__device__ __half g_Wt[(size_t)4*HID*HID];           // transposed weights [N,K] fp16
__device__ __half g_Mc[BATCH*SEQ];                   // compact keep-mask (1 kept, 0 pad)
__device__ int    g_Idx[BATCH*SEQ];                  // kept-position indices
__device__ int    g_Cnt[BATCH];                      // kept count per batch

// ---------------- PTX helpers (base compute_103 features only) --------------
__device__ __forceinline__ uint32_t smem_u32(const void* p) {
    uint32_t a;
    asm("{ .reg .u64 t; cvta.to.shared.u64 t, %1; cvt.u32.u64 %0, t; }"
        : "=r"(a) : "l"(p));
    return a;
}
__device__ __forceinline__ void cpa16(uint32_t dst, const void* src) {
    asm volatile("cp.async.cg.shared.global [%0], [%1], 16;"
                 :: "r"(dst), "l"(src));
}
// zfill variant: copies min(16, n) bytes, zero-fills the rest (n=0 -> all zeros)
__device__ __forceinline__ void cpa16z(uint32_t dst, const void* src, uint32_t n) {
    asm volatile("cp.async.cg.shared.global [%0], [%1], 16, %2;"
                 :: "r"(dst), "l"(src), "r"(n));
}
#define CPA_COMMIT() asm volatile("cp.async.commit_group;" ::: "memory")
#define CPA_WAIT(n)  asm volatile("cp.async.wait_group %0;" :: "n"(n) : "memory")

__device__ __forceinline__ void ldsm4(uint32_t r[4], uint32_t addr) {
    asm volatile("ldmatrix.sync.aligned.m8n8.x4.shared.b16 {%0,%1,%2,%3}, [%4];"
                 : "=r"(r[0]), "=r"(r[1]), "=r"(r[2]), "=r"(r[3]) : "r"(addr));
}
__device__ __forceinline__ void ldsm4t(uint32_t r[4], uint32_t addr) {
    asm volatile("ldmatrix.sync.aligned.m8n8.x4.trans.shared.b16 {%0,%1,%2,%3}, [%4];"
                 : "=r"(r[0]), "=r"(r[1]), "=r"(r[2]), "=r"(r[3]) : "r"(addr));
}
__device__ __forceinline__ void ldsm2t(uint32_t r[2], uint32_t addr) {
    asm volatile("ldmatrix.sync.aligned.m8n8.x2.trans.shared.b16 {%0,%1}, [%2];"
                 : "=r"(r[0]), "=r"(r[1]) : "r"(addr));
}
__device__ __forceinline__ void mma_f16(float c[4], const uint32_t a[4],
                                        uint32_t b0, uint32_t b1) {
    asm volatile(
        "mma.sync.aligned.m16n8k16.row.col.f32.f16.f16.f32 "
        "{%0,%1,%2,%3}, {%4,%5,%6,%7}, {%8,%9}, {%0,%1,%2,%3};"
        : "+f"(c[0]), "+f"(c[1]), "+f"(c[2]), "+f"(c[3])
        : "r"(a[0]), "r"(a[1]), "r"(a[2]), "r"(a[3]), "r"(b0), "r"(b1));
}
__device__ __forceinline__ uint32_t packh(float v0, float v1) {
    uint32_t d;
    asm("cvt.rn.f16x2.f32 %0, %1, %2;" : "=r"(d) : "f"(v1), "f"(v0));
    return d;
}
__device__ __forceinline__ uint32_t ex2h2(uint32_t x) {
    uint32_t y;
    asm("ex2.approx.f16x2 %0, %1;" : "=r"(y) : "r"(x));
    return y;
}
__device__ __forceinline__ uint32_t hmul2(uint32_t a, uint32_t b) {
    uint32_t d;
    asm("mul.f16x2 %0, %1, %2;" : "=r"(d) : "r"(a), "r"(b));
    return d;
}
#define SWZ(o) ((o) ^ ((((uint32_t)(o)) >> 3) & 0x70u))

#define LOG2E      1.4426950408889634f
#define SCALE_L2   (0.125f * LOG2E)

// ---------------- pre-passes -------------------------------------------------
__global__ void xconv_kernel(const float* __restrict__ src,
                             __half* __restrict__ dst, int n4)
{
    int i = blockIdx.x * blockDim.x + threadIdx.x;
    if (i >= n4) return;
    float4 v = ((const float4*)src)[i];
    uint2 o;
    o.x = packh(v.x, v.y);
    o.y = packh(v.z, v.w);
    ((uint2*)dst)[i] = o;
}

// ordered mask compaction: one block per batch, deterministic scan
__global__ void compact_kernel(const float* __restrict__ mask)
{
    __shared__ int cnts[256];
    __shared__ int offs[256];
    const int b = blockIdx.x;
    const int t = threadIdx.x;
    const float* m = mask + (size_t)b * SEQ;

    int keep[8];
    int c = 0;
    #pragma unroll
    for (int j = 0; j < 8; j++) {
        keep[j] = (m[t * 8 + j] == 0.0f) ? 1 : 0;   // mask==0 -> key kept
        c += keep[j];
    }
    cnts[t] = c;
    __syncthreads();
    if (t == 0) {
        int acc = 0;
        for (int i = 0; i < 256; i++) { offs[i] = acc; acc += cnts[i]; }
        g_Cnt[b] = acc;
    }
    __syncthreads();
    int o = offs[t];
    #pragma unroll
    for (int j = 0; j < 8; j++)
        if (keep[j]) g_Idx[b * SEQ + (o++)] = t * 8 + j;
    __syncthreads();
    const int cnt = g_Cnt[b];
    for (int i = t; i < SEQ; i += 256) {
        g_Mc[b * SEQ + i] = __float2half_rn(i < cnt ? 1.0f : 0.0f);
        if (i >= cnt) g_Idx[b * SEQ + i] = 0;
    }
}

__global__ void wconv_kernel(const float* __restrict__ Wq, const float* __restrict__ Wk,
                             const float* __restrict__ Wv, const float* __restrict__ Wo)
{
    __shared__ float t[32][33];
    const int z = blockIdx.z;
    const float* W = (z == 0) ? Wq : (z == 1) ? Wk : (z == 2) ? Wv : Wo;
    __half* T = g_Wt + (size_t)z * HID * HID;
    const int n0 = blockIdx.x * 32;
    const int k0 = blockIdx.y * 32;
    const int tx = threadIdx.x, ty = threadIdx.y;

    #pragma unroll
    for (int i = 0; i < 32; i += 8)
        t[ty + i][tx] = W[(size_t)(k0 + ty + i) * HID + n0 + tx];
    __syncthreads();
    #pragma unroll
    for (int i = 0; i < 32; i += 8)
        T[(size_t)(n0 + ty + i) * HID + k0 + tx] = __float2half_rn(t[tx][ty + i]);
}

// ---------------- fp16 GEMM: 128 thr, 4 warps x (64x64), K-chunk 64 ---------
// A-side optionally gathered through an index array (fused mask compaction).
#define LDA        72
#define PART_BYTES (128 * LDA * 2)   // 18432
#define BUF_BYTES  (2 * PART_BYTES)  // 36864
#define GEMM_SMEM  (2 * BUF_BYTES)   // 73728

// mode: 0 = fp32 row-major; 1 = fp16 permuted (Q, global rows);
//       2 = fp16 permuted, Ch pre-offset to batch, local rows (KV, gathered A)
__device__ __forceinline__ void hmma_gemm(
    const __half* __restrict__ A, const __half* __restrict__ B,
    const float* __restrict__ bias, float escale, float* __restrict__ C,
    __half* __restrict__ Ch, int mode, int row0, int col0,
    const int* __restrict__ idxp, int cnt)
{
    extern __shared__ char sm[];
    const uint32_t sbase = smem_u32(sm);
    const int tid  = threadIdx.x;
    const int wid  = tid >> 5, lane = tid & 31;
    const int warp_m = wid >> 1;
    const int warp_n = wid & 1;

    // per-thread A-row mapping is chunk-invariant: row = tid/8 + it*16, seg = tid%8
    const int rthr = tid >> 3;
    const int seg  = tid & 7;
    uint32_t aoff[8];
    uint32_t asz[8];
    #pragma unroll
    for (int it = 0; it < 8; ++it) {
        const int r = row0 + rthr + it * 16;
        if (idxp) {
            aoff[it] = (uint32_t)idxp[r] * (KDIM * 2) + seg * 16;
            asz[it]  = (r < cnt) ? 16u : 0u;
        } else {
            aoff[it] = (uint32_t)r * (KDIM * 2) + seg * 16;
            asz[it]  = 16u;
        }
    }
    const __half* Bp = B + (size_t)col0 * KDIM;

    auto load_chunk = [&](int chunk, int buf) {
        const int k0b = chunk * 128;   // byte offset along K
        const uint32_t dbaseA = sbase + buf * BUF_BYTES;
        #pragma unroll
        for (int it = 0; it < 8; ++it) {
            const int row = rthr + it * 16;
            cpa16z(dbaseA + (uint32_t)row * (LDA * 2) + seg * 16,
                   (const char*)A + aoff[it] + k0b, asz[it]);
        }
        const uint32_t dbaseB = dbaseA + PART_BYTES;
        #pragma unroll
        for (int it = 0; it < 8; ++it) {
            const int row = rthr + it * 16;
            cpa16(dbaseB + (uint32_t)row * (LDA * 2) + seg * 16,
                  (const char*)Bp + (size_t)row * (KDIM * 2) + seg * 16 + k0b);
        }
        CPA_COMMIT();
    };

    float c[4][8][4];
    #pragma unroll
    for (int mf = 0; mf < 4; mf++)
        #pragma unroll
        for (int nf = 0; nf < 8; nf++)
            #pragma unroll
            for (int j = 0; j < 4; j++) c[mf][nf][j] = 0.0f;

    load_chunk(0, 0);
    int buf = 0;

    for (int i = 0; i < KDIM / 64; ++i) {
        if (i + 1 < KDIM / 64) {
            load_chunk(i + 1, buf ^ 1);
            CPA_WAIT(1);
        } else {
            CPA_WAIT(0);
        }
        __syncthreads();

        const uint32_t base = sbase + buf * BUF_BYTES;
        #pragma unroll
        for (int ks = 0; ks < 64; ks += 16) {
            uint32_t ah[4][4];
            #pragma unroll
            for (int mf = 0; mf < 4; mf++) {
                int row = warp_m * 64 + mf * 16 + (lane & 15);
                int col = ks + ((lane & 16) ? 8 : 0);
                ldsm4(ah[mf], base + (uint32_t)row * (LDA * 2) + col * 2);
            }
            #pragma unroll
            for (int nf4 = 0; nf4 < 4; nf4++) {
                int nrow = warp_n * 64 + nf4 * 16 + (lane & 7) + ((lane & 16) ? 8 : 0);
                int col  = ks + ((lane & 8) ? 8 : 0);
                uint32_t tb[4];
                ldsm4(tb, base + PART_BYTES + (uint32_t)nrow * (LDA * 2) + col * 2);
                const int j = 2 * nf4;
                #pragma unroll
                for (int mf = 0; mf < 4; mf++) {
                    mma_f16(c[mf][j],   ah[mf], tb[0], tb[1]);
                    mma_f16(c[mf][j+1], ah[mf], tb[2], tb[3]);
                }
            }
        }
        __syncthreads();
        buf ^= 1;
    }

    const int rbase = row0 + warp_m * 64 + (lane >> 2);
    const int cbase = col0 + warp_n * 64 + 2 * (lane & 3);
    #pragma unroll
    for (int mf = 0; mf < 4; mf++) {
        #pragma unroll
        for (int nf = 0; nf < 8; nf++) {
            const int gc = cbase + nf * 8;
            const float b0 = bias[gc], b1 = bias[gc + 1];
            #pragma unroll
            for (int half = 0; half < 2; half++) {
                const int gr = rbase + mf * 16 + half * 8;
                float v0 = (c[mf][nf][half*2]   + b0) * escale;
                float v1 = (c[mf][nf][half*2+1] + b1) * escale;
                if (mode == 0) {
                    float* dst = C + (size_t)gr * HID + gc;
                    *(float2*)dst = make_float2(v0, v1);
                } else {
                    const int h = gc >> 6;
                    const int d = gc & 63;
                    size_t off;
                    if (mode == 1) {
                        const int bb = gr >> 11;
                        const int lq = gr & (SEQ - 1);
                        off = ((size_t)((bb * HEADS + h) * SEQ + lq)) * DH + d;
                    } else {
                        off = ((size_t)(h * SEQ + gr)) * DH + d;
                    }
                    *(uint32_t*)(Ch + off) = packh(v0, v1);
                }
            }
        }
    }
}

__global__ __launch_bounds__(128, 2)
void qkv_tc(const float* __restrict__ bq, const float* __restrict__ bk,
            const float* __restrict__ bv)
{
    const int z = blockIdx.z;
    if (z == 0) {
        hmma_gemm(g_X, g_Wt, bq, SCALE_L2, nullptr, g_Q, 1,
                  blockIdx.y * 128, blockIdx.x * 128, nullptr, 0);
    } else {
        const int b   = blockIdx.y >> 4;
        const int m0  = (blockIdx.y & 15) * 128;
        const int cnt = g_Cnt[b];
        const int pad = (cnt + 127) & ~127;
        if (m0 >= pad) return;
        __half* Ch = ((z == 1) ? g_K : g_V) + (size_t)b * HEADS * SEQ * DH;
        hmma_gemm(g_X + (size_t)b * SEQ * HID,
                  g_Wt + (size_t)z * HID * HID,
                  (z == 1) ? bk : bv, 1.0f, nullptr, Ch, 2,
                  m0, blockIdx.x * 128, g_Idx + b * SEQ, cnt);
    }
}

__global__ __launch_bounds__(128, 2)
void out_tc(const float* __restrict__ bo, float* __restrict__ out)
{
    hmma_gemm(g_O, g_Wt + (size_t)3 * HID * HID, bo, 1.0f, out, nullptr, 0,
              blockIdx.y * 128, blockIdx.x * 128, nullptr, 0);
}

// ---------------- fp16 flash attention (q-tile 128, 2 CTAs/SM) --------------
#define ATT_LDS   72
#define ATT_PART  (64 * ATT_LDS * 2)          // 9216
#define ATT_BUF   (2 * ATT_PART)              // 18432
#define ATT_Q     16384                       // Q: 128 rows x 128B
#define ATT_MASK  (ATT_Q + 2 * ATT_BUF)       // 53248
#define ATT_SMEM  (ATT_MASK + 256)
#define ATT_THR   128

__global__ __launch_bounds__(ATT_THR, 2)
void attn_mma()
{
    extern __shared__ char sm[];
    const uint32_t sbase = smem_u32(sm);
    const int tid  = threadIdx.x;
    const int wid  = tid >> 5, lane = tid & 31;
    const int q0   = blockIdx.x * 128;
    const int h    = blockIdx.y;
    const int b    = blockIdx.z;

    const int cnt = g_Cnt[b];
    const int nkt = (cnt + 63) >> 6;          // compact k-tiles

    const size_t bh_off = (size_t)(b * HEADS + h) * SEQ * DH;
    const __half* Qg = g_Q + bh_off + (size_t)q0 * DH;
    const __half* Kg = g_K + bh_off;
    const __half* Vg = g_V + bh_off;
    const __half* mrow = g_Mc + (size_t)b * SEQ;

    auto load_tile = [&](int i, int buf) {
        const int k0 = i * 64;
        const __half* srcs[2] = { Kg + (size_t)k0 * DH, Vg + (size_t)k0 * DH };
        #pragma unroll
        for (int p = 0; p < 2; ++p) {
            const uint32_t base = sbase + ATT_Q + buf * ATT_BUF + p * ATT_PART;
            #pragma unroll
            for (int it = 0; it < 4; ++it) {
                int idx = tid + it * ATT_THR;
                int row = idx >> 3;
                int seg = idx & 7;
                cpa16(base + (uint32_t)row * (ATT_LDS * 2) + seg * 16,
                      srcs[p] + (size_t)row * DH + seg * 8);
            }
        }
        if (tid < 8)
            cpa16(sbase + ATT_MASK + buf * 128 + tid * 16, mrow + k0 + tid * 8);
        CPA_COMMIT();
    };

    // ones-column (V cols 64-71) for both buffers
    {
        int bufi = tid >> 6;
        int row  = tid & 63;
        uint4* p = (uint4*)(sm + ATT_Q + bufi * ATT_BUF + ATT_PART
                            + row * (ATT_LDS * 2) + 128);
        *p = make_uint4(0x00003C00u, 0u, 0u, 0u);
    }

    // stage Q (128 rows)
    {
        #pragma unroll
        for (int it = 0; it < 8; ++it) {
            int idx = tid + it * ATT_THR;
            int row = idx >> 3;
            int seg = idx & 7;
            cpa16(sbase + SWZ((uint32_t)row * 128 + seg * 16),
                  Qg + (size_t)row * DH + seg * 8);
        }
        CPA_COMMIT();
    }
    load_tile(0, 0);
    CPA_WAIT(0);
    __syncthreads();

    // hoist Q fragments
    uint32_t qf[2][4][4];
    #pragma unroll
    for (int t = 0; t < 4; ++t)
        #pragma unroll
        for (int mf = 0; mf < 2; mf++) {
            const int row = wid * 32 + mf * 16 + (lane & 15);
            const uint32_t colb = (uint32_t)(t * 16 + ((lane & 16) ? 8 : 0)) * 2;
            ldsm4(qf[mf][t], sbase + SWZ((uint32_t)row * 128 + colb));
        }

    // hoist ones-column b-fragment
    uint32_t eones[2];
    {
        const int krow = lane & 15;
        ldsm2t(eones, sbase + ATT_Q + ATT_PART + (uint32_t)krow * (ATT_LDS * 2) + 128);
    }

    float o[2][8][4];
    float oE[2][4];
    #pragma unroll
    for (int mf = 0; mf < 2; mf++) {
        #pragma unroll
        for (int j = 0; j < 8; j++)
            #pragma unroll
            for (int cc = 0; cc < 4; cc++) o[mf][j][cc] = 0.0f;
        #pragma unroll
        for (int cc = 0; cc < 4; cc++) oE[mf][cc] = 0.0f;
    }

    for (int i = 0; i < nkt; ++i) {
        const int buf = i & 1;
        if (i + 1 < nkt) {
            load_tile(i + 1, buf ^ 1);
            CPA_WAIT(1);
        } else {
            CPA_WAIT(0);
        }
        __syncthreads();

        const uint32_t kbase = sbase + ATT_Q + buf * ATT_BUF;

        // ---- S = Q @ K^T ----
        float s[2][8][4];
        #pragma unroll
        for (int mf = 0; mf < 2; mf++)
            #pragma unroll
            for (int j = 0; j < 8; j++)
                #pragma unroll
                for (int cc = 0; cc < 4; cc++) s[mf][j][cc] = 0.0f;

        #pragma unroll
        for (int t = 0; t < 4; ++t) {
            #pragma unroll
            for (int nf2 = 0; nf2 < 4; ++nf2) {
                const int nrow = nf2 * 16 + (lane & 7) + ((lane & 16) ? 8 : 0);
                const uint32_t colb = (uint32_t)(t * 16 + ((lane & 8) ? 8 : 0)) * 2;
                uint32_t th[4];
                ldsm4(th, kbase + (uint32_t)nrow * (ATT_LDS * 2) + colb);
                const int j = 2 * nf2;
                #pragma unroll
                for (int mf = 0; mf < 2; mf++) {
                    mma_f16(s[mf][j],   qf[mf][t], th[0], th[1]);
                    mma_f16(s[mf][j+1], qf[mf][t], th[2], th[3]);
                }
            }
        }

        // ---- P = exp2(S) (f16x2), zero pad cols ----
        uint32_t ph[2][8][2];
        uint32_t mh[8];
        #pragma unroll
        for (int j = 0; j < 8; j++)
            mh[j] = *(const uint32_t*)(sm + ATT_MASK + buf * 128
                                       + (8 * j + 2 * (lane & 3)) * 2);
        #pragma unroll
        for (int mf = 0; mf < 2; mf++)
            #pragma unroll
            for (int j = 0; j < 8; j++) {
                ph[mf][j][0] = hmul2(ex2h2(packh(s[mf][j][0], s[mf][j][1])), mh[j]);
                ph[mf][j][1] = hmul2(ex2h2(packh(s[mf][j][2], s[mf][j][3])), mh[j]);
            }

        // ---- O += P @ V; l += P @ ones ----
        #pragma unroll
        for (int t = 0; t < 4; ++t) {
            uint32_t a0[4] = { ph[0][2*t][0], ph[0][2*t][1],
                               ph[0][2*t+1][0], ph[0][2*t+1][1] };
            uint32_t a1[4] = { ph[1][2*t][0], ph[1][2*t][1],
                               ph[1][2*t+1][0], ph[1][2*t+1][1] };
            mma_f16(oE[0], a0, eones[0], eones[1]);
            mma_f16(oE[1], a1, eones[0], eones[1]);
            #pragma unroll
            for (int nf2 = 0; nf2 < 4; ++nf2) {
                const int krow = t * 16 + (lane & 15);
                const uint32_t colb = (uint32_t)(nf2 * 16 + ((lane & 16) ? 8 : 0)) * 2;
                uint32_t tv[4];
                ldsm4t(tv, kbase + ATT_PART + (uint32_t)krow * (ATT_LDS * 2) + colb);
                const int j = 2 * nf2;
                mma_f16(o[0][j],   a0, tv[0], tv[1]);
                mma_f16(o[0][j+1], a0, tv[2], tv[3]);
                mma_f16(o[1][j],   a1, tv[0], tv[1]);
                mma_f16(o[1][j+1], a1, tv[2], tv[3]);
            }
        }
        __syncthreads();
    }

    // ---- epilogue ----
    #pragma unroll
    for (int mf = 0; mf < 2; mf++) {
        const float l0 = __shfl_sync(0xffffffffu, oE[mf][0], lane & ~3);
        const float l1 = __shfl_sync(0xffffffffu, oE[mf][2], lane & ~3);
        const float inv0 = 1.0f / l0;
        const float inv1 = 1.0f / l1;
        const int r0 = q0 + wid * 32 + mf * 16 + (lane >> 2);
        #pragma unroll
        for (int j = 0; j < 8; j++) {
            const int col = h * 64 + 8 * j + 2 * (lane & 3);
            #pragma unroll
            for (int half = 0; half < 2; half++) {
                const int gr = r0 + half * 8;
                const float inv = half ? inv1 : inv0;
                float v0 = o[mf][j][half*2]     * inv;
                float v1 = o[mf][j][half*2 + 1] * inv;
                size_t off = (size_t)(b * SEQ + gr) * HID + col;
                *(uint32_t*)(g_O + off) = packh(v0, v1);
            }
        }
    }
}

// ---------------------------------------------------------------------------
extern "C" void kernel_launch(void* const* d_in, const int* in_sizes, int n_in,
                              void* d_out, int out_size)
{
    (void)in_sizes; (void)n_in; (void)out_size;
    const float* x    = (const float*)d_in[0];
    const float* mask = (const float*)d_in[1];
    const float* Wq   = (const float*)d_in[2];
    const float* bq   = (const float*)d_in[3];
    const float* Wk   = (const float*)d_in[4];
    const float* bk   = (const float*)d_in[5];
    const float* Wv   = (const float*)d_in[6];
    const float* bv   = (const float*)d_in[7];
    const float* Wo   = (const float*)d_in[8];
    const float* bo   = (const float*)d_in[9];
    float* out = (float*)d_out;

    __half* xh;
    cudaGetSymbolAddress((void**)&xh, g_X);

    // 0) pre-passes (xgather fused into qkv_tc via indexed cp.async)
    const int n4 = MROWS * HID / 4;
    xconv_kernel<<<(n4 + 255) / 256, 256>>>(x, xh, n4);
    compact_kernel<<<BATCH, 256>>>(mask);
    wconv_kernel<<<dim3(32, 32, 4), dim3(32, 8)>>>(Wq, Wk, Wv, Wo);

    // 1) QKV projections (Q full; K/V gather compacted rows inline)
    cudaFuncSetAttribute(qkv_tc, cudaFuncAttributeMaxDynamicSharedMemorySize, GEMM_SMEM);
    qkv_tc<<<dim3(HID / 128, MROWS / 128, 3), 128, GEMM_SMEM>>>(bq, bk, bv);

    // 2) attention over compacted keys (q-tile 128, 2 CTAs/SM)
    cudaFuncSetAttribute(attn_mma, cudaFuncAttributeMaxDynamicSharedMemorySize, ATT_SMEM);
    attn_mma<<<dim3(SEQ / 128, HEADS, BATCH), ATT_THR, ATT_SMEM>>>();

    // 3) output projection
    cudaFuncSetAttribute(out_tc, cudaFuncAttributeMaxDynamicSharedMemorySize, GEMM_SMEM);
    out_tc<<<dim3(HID / 128, MROWS / 128), 128, GEMM_SMEM>>>(bo, out);
}

// round 16
// speedup vs baseline: 1.0244x; 1.0244x over previous
#include <cuda_runtime.h>
#include <cuda_fp16.h>
#include <cstdint>

#define HEADS 16
#define HID   1024
#define DH    64
#define BATCH 2
#define SEQ   2048
#define MROWS (BATCH*SEQ)
#define KDIM  1024

// ---------------- scratch (__device__ globals; alloc-free rule) -------------
__device__ __half g_Q[(size_t)BATCH*HEADS*SEQ*DH];   // pre-scaled by SCALE*log2e
__device__ __half g_K[(size_t)BATCH*HEADS*SEQ*DH];   // compact-domain rows
__device__ __half g_V[(size_t)BATCH*HEADS*SEQ*DH];   // compact-domain rows

__device__ __half g_X [(size_t)MROWS*HID];
__device__ __half g_O [(size_t)MROWS*HID];
__device__ __half g_Wt[(size_t)4*HID*HID];           // transposed weights [N,K] fp16
__device__ __half g_Mc[BATCH*SEQ];                   // compact keep-mask (1 kept, 0 pad)
__device__ int    g_Idx[BATCH*SEQ];                  // kept-position indices
__device__ int    g_Cnt[BATCH];                      // kept count per batch

// cross-phase dependency flags (zeroed each call by compact_kernel)
__device__ int    g_FlagQ[256];                      // per Q-GEMM CTA
__device__ int    g_CntKV[BATCH];                    // K+V CTA arrivals per batch (target 256)
__device__ int    g_CntO[32];                        // attn arrivals per (b, q-tile) (target 16)

// ---------------- PTX helpers (base compute_103 features only) --------------
__device__ __forceinline__ uint32_t smem_u32(const void* p) {
    uint32_t a;
    asm("{ .reg .u64 t; cvta.to.shared.u64 t, %1; cvt.u32.u64 %0, t; }"
        : "=r"(a) : "l"(p));
    return a;
}
__device__ __forceinline__ void cpa16(uint32_t dst, const void* src) {
    asm volatile("cp.async.cg.shared.global [%0], [%1], 16;"
                 :: "r"(dst), "l"(src));
}
__device__ __forceinline__ void cpa16z(uint32_t dst, const void* src, uint32_t n) {
    asm volatile("cp.async.cg.shared.global [%0], [%1], 16, %2;"
                 :: "r"(dst), "l"(src), "r"(n));
}
#define CPA_COMMIT() asm volatile("cp.async.commit_group;" ::: "memory")
#define CPA_WAIT(n)  asm volatile("cp.async.wait_group %0;" :: "n"(n) : "memory")

__device__ __forceinline__ void ldsm4(uint32_t r[4], uint32_t addr) {
    asm volatile("ldmatrix.sync.aligned.m8n8.x4.shared.b16 {%0,%1,%2,%3}, [%4];"
                 : "=r"(r[0]), "=r"(r[1]), "=r"(r[2]), "=r"(r[3]) : "r"(addr));
}
__device__ __forceinline__ void ldsm4t(uint32_t r[4], uint32_t addr) {
    asm volatile("ldmatrix.sync.aligned.m8n8.x4.trans.shared.b16 {%0,%1,%2,%3}, [%4];"
                 : "=r"(r[0]), "=r"(r[1]), "=r"(r[2]), "=r"(r[3]) : "r"(addr));
}
__device__ __forceinline__ void ldsm2t(uint32_t r[2], uint32_t addr) {
    asm volatile("ldmatrix.sync.aligned.m8n8.x2.trans.shared.b16 {%0,%1}, [%2];"
                 : "=r"(r[0]), "=r"(r[1]) : "r"(addr));
}
__device__ __forceinline__ void mma_f16(float c[4], const uint32_t a[4],
                                        uint32_t b0, uint32_t b1) {
    asm volatile(
        "mma.sync.aligned.m16n8k16.row.col.f32.f16.f16.f32 "
        "{%0,%1,%2,%3}, {%4,%5,%6,%7}, {%8,%9}, {%0,%1,%2,%3};"
        : "+f"(c[0]), "+f"(c[1]), "+f"(c[2]), "+f"(c[3])
        : "r"(a[0]), "r"(a[1]), "r"(a[2]), "r"(a[3]), "r"(b0), "r"(b1));
}
__device__ __forceinline__ uint32_t packh(float v0, float v1) {
    uint32_t d;
    asm("cvt.rn.f16x2.f32 %0, %1, %2;" : "=r"(d) : "f"(v1), "f"(v0));
    return d;
}
__device__ __forceinline__ uint32_t ex2h2(uint32_t x) {
    uint32_t y;
    asm("ex2.approx.f16x2 %0, %1;" : "=r"(y) : "r"(x));
    return y;
}
__device__ __forceinline__ uint32_t hmul2(uint32_t a, uint32_t b) {
    uint32_t d;
    asm("mul.f16x2 %0, %1, %2;" : "=r"(d) : "r"(a), "r"(b));
    return d;
}
__device__ __forceinline__ void spin_ge(const int* p, int target) {
    int v;
    while (true) {
        asm volatile("ld.acquire.gpu.s32 %0, [%1];" : "=r"(v) : "l"(p) : "memory");
        if (v >= target) break;
        __nanosleep(128);
    }
}
#define SWZ(o) ((o) ^ ((((uint32_t)(o)) >> 3) & 0x70u))

#define LOG2E      1.4426950408889634f
#define SCALE_L2   (0.125f * LOG2E)

// ---------------- pre-passes -------------------------------------------------
__global__ void xconv_kernel(const float* __restrict__ src,
                             __half* __restrict__ dst, int n4)
{
    int i = blockIdx.x * blockDim.x + threadIdx.x;
    if (i >= n4) return;
    float4 v = ((const float4*)src)[i];
    uint2 o;
    o.x = packh(v.x, v.y);
    o.y = packh(v.z, v.w);
    ((uint2*)dst)[i] = o;
}

// ordered mask compaction + flag reset: one block per batch
__global__ void compact_kernel(const float* __restrict__ mask)
{
    __shared__ int cnts[256];
    __shared__ int offs[256];
    const int b = blockIdx.x;
    const int t = threadIdx.x;
    const float* m = mask + (size_t)b * SEQ;

    if (b == 0) {                       // reset cross-phase flags
        g_FlagQ[t] = 0;
        if (t < BATCH) g_CntKV[t] = 0;
        if (t < 32)    g_CntO[t]  = 0;
    }

    int keep[8];
    int c = 0;
    #pragma unroll
    for (int j = 0; j < 8; j++) {
        keep[j] = (m[t * 8 + j] == 0.0f) ? 1 : 0;   // mask==0 -> key kept
        c += keep[j];
    }
    cnts[t] = c;
    __syncthreads();
    if (t == 0) {
        int acc = 0;
        for (int i = 0; i < 256; i++) { offs[i] = acc; acc += cnts[i]; }
        g_Cnt[b] = acc;
    }
    __syncthreads();
    int o = offs[t];
    #pragma unroll
    for (int j = 0; j < 8; j++)
        if (keep[j]) g_Idx[b * SEQ + (o++)] = t * 8 + j;
    __syncthreads();
    const int cnt = g_Cnt[b];
    for (int i = t; i < SEQ; i += 256) {
        g_Mc[b * SEQ + i] = __float2half_rn(i < cnt ? 1.0f : 0.0f);
        if (i >= cnt) g_Idx[b * SEQ + i] = 0;
    }
}

__global__ void wconv_kernel(const float* __restrict__ Wq, const float* __restrict__ Wk,
                             const float* __restrict__ Wv, const float* __restrict__ Wo)
{
    __shared__ float t[32][33];
    const int z = blockIdx.z;
    const float* W = (z == 0) ? Wq : (z == 1) ? Wk : (z == 2) ? Wv : Wo;
    __half* T = g_Wt + (size_t)z * HID * HID;
    const int n0 = blockIdx.x * 32;
    const int k0 = blockIdx.y * 32;
    const int tx = threadIdx.x, ty = threadIdx.y;

    #pragma unroll
    for (int i = 0; i < 32; i += 8)
        t[ty + i][tx] = W[(size_t)(k0 + ty + i) * HID + n0 + tx];
    __syncthreads();
    #pragma unroll
    for (int i = 0; i < 32; i += 8)
        T[(size_t)(n0 + ty + i) * HID + k0 + tx] = __float2half_rn(t[tx][ty + i]);
}

// ---------------- fp16 GEMM body: 128 thr, 4 warps x (64x64), K-chunk 64 ----
#define LDA        72
#define PART_BYTES (128 * LDA * 2)   // 18432
#define BUF_BYTES  (2 * PART_BYTES)  // 36864
#define GEMM_SMEM  (2 * BUF_BYTES)   // 73728

// mode: 0 = fp32 row-major; 1 = fp16 permuted (Q, global rows);
//       2 = fp16 permuted, Ch pre-offset to batch, local rows (KV, gathered A)
__device__ __forceinline__ void hmma_gemm(
    const __half* __restrict__ A, const __half* __restrict__ B,
    const float* __restrict__ bias, float escale, float* __restrict__ C,
    __half* __restrict__ Ch, int mode, int row0, int col0,
    const int* __restrict__ idxp, int cnt)
{
    extern __shared__ char sm[];
    const uint32_t sbase = smem_u32(sm);
    const int tid  = threadIdx.x;
    const int wid  = tid >> 5, lane = tid & 31;
    const int warp_m = wid >> 1;
    const int warp_n = wid & 1;

    const int rthr = tid >> 3;
    const int seg  = tid & 7;
    uint32_t aoff[8];
    uint32_t asz[8];
    #pragma unroll
    for (int it = 0; it < 8; ++it) {
        const int r = row0 + rthr + it * 16;
        if (idxp) {
            aoff[it] = (uint32_t)idxp[r] * (KDIM * 2) + seg * 16;
            asz[it]  = (r < cnt) ? 16u : 0u;
        } else {
            aoff[it] = (uint32_t)r * (KDIM * 2) + seg * 16;
            asz[it]  = 16u;
        }
    }
    const __half* Bp = B + (size_t)col0 * KDIM;

    auto load_chunk = [&](int chunk, int buf) {
        const int k0b = chunk * 128;
        const uint32_t dbaseA = sbase + buf * BUF_BYTES;
        #pragma unroll
        for (int it = 0; it < 8; ++it) {
            const int row = rthr + it * 16;
            cpa16z(dbaseA + (uint32_t)row * (LDA * 2) + seg * 16,
                   (const char*)A + aoff[it] + k0b, asz[it]);
        }
        const uint32_t dbaseB = dbaseA + PART_BYTES;
        #pragma unroll
        for (int it = 0; it < 8; ++it) {
            const int row = rthr + it * 16;
            cpa16(dbaseB + (uint32_t)row * (LDA * 2) + seg * 16,
                  (const char*)Bp + (size_t)row * (KDIM * 2) + seg * 16 + k0b);
        }
        CPA_COMMIT();
    };

    float c[4][8][4];
    #pragma unroll
    for (int mf = 0; mf < 4; mf++)
        #pragma unroll
        for (int nf = 0; nf < 8; nf++)
            #pragma unroll
            for (int j = 0; j < 4; j++) c[mf][nf][j] = 0.0f;

    load_chunk(0, 0);
    int buf = 0;

    for (int i = 0; i < KDIM / 64; ++i) {
        if (i + 1 < KDIM / 64) {
            load_chunk(i + 1, buf ^ 1);
            CPA_WAIT(1);
        } else {
            CPA_WAIT(0);
        }
        __syncthreads();

        const uint32_t base = sbase + buf * BUF_BYTES;
        #pragma unroll
        for (int ks = 0; ks < 64; ks += 16) {
            uint32_t ah[4][4];
            #pragma unroll
            for (int mf = 0; mf < 4; mf++) {
                int row = warp_m * 64 + mf * 16 + (lane & 15);
                int col = ks + ((lane & 16) ? 8 : 0);
                ldsm4(ah[mf], base + (uint32_t)row * (LDA * 2) + col * 2);
            }
            #pragma unroll
            for (int nf4 = 0; nf4 < 4; nf4++) {
                int nrow = warp_n * 64 + nf4 * 16 + (lane & 7) + ((lane & 16) ? 8 : 0);
                int col  = ks + ((lane & 8) ? 8 : 0);
                uint32_t tb[4];
                ldsm4(tb, base + PART_BYTES + (uint32_t)nrow * (LDA * 2) + col * 2);
                const int j = 2 * nf4;
                #pragma unroll
                for (int mf = 0; mf < 4; mf++) {
                    mma_f16(c[mf][j],   ah[mf], tb[0], tb[1]);
                    mma_f16(c[mf][j+1], ah[mf], tb[2], tb[3]);
                }
            }
        }
        __syncthreads();
        buf ^= 1;
    }

    const int rbase = row0 + warp_m * 64 + (lane >> 2);
    const int cbase = col0 + warp_n * 64 + 2 * (lane & 3);
    #pragma unroll
    for (int mf = 0; mf < 4; mf++) {
        #pragma unroll
        for (int nf = 0; nf < 8; nf++) {
            const int gc = cbase + nf * 8;
            const float b0 = bias[gc], b1 = bias[gc + 1];
            #pragma unroll
            for (int half = 0; half < 2; half++) {
                const int gr = rbase + mf * 16 + half * 8;
                float v0 = (c[mf][nf][half*2]   + b0) * escale;
                float v1 = (c[mf][nf][half*2+1] + b1) * escale;
                if (mode == 0) {
                    float* dst = C + (size_t)gr * HID + gc;
                    *(float2*)dst = make_float2(v0, v1);
                } else {
                    const int h = gc >> 6;
                    const int d = gc & 63;
                    size_t off;
                    if (mode == 1) {
                        const int bb = gr >> 11;
                        const int lq = gr & (SEQ - 1);
                        off = ((size_t)((bb * HEADS + h) * SEQ + lq)) * DH + d;
                    } else {
                        off = ((size_t)(h * SEQ + gr)) * DH + d;
                    }
                    *(uint32_t*)(Ch + off) = packh(v0, v1);
                }
            }
        }
    }
}

// ---------------- attention body (q-tile 128) --------------------------------
#define ATT_LDS   72
#define ATT_PART  (64 * ATT_LDS * 2)          // 9216
#define ATT_BUF   (2 * ATT_PART)              // 18432
#define ATT_Q     16384
#define ATT_MASK  (ATT_Q + 2 * ATT_BUF)       // 53248
#define ATT_THR   128

__device__ __forceinline__ void attn_body(int b, int h, int q0)
{
    extern __shared__ char sm[];
    const uint32_t sbase = smem_u32(sm);
    const int tid  = threadIdx.x;
    const int wid  = tid >> 5, lane = tid & 31;

    const int cnt = g_Cnt[b];
    const int nkt = (cnt + 63) >> 6;

    const size_t bh_off = (size_t)(b * HEADS + h) * SEQ * DH;
    const __half* Qg = g_Q + bh_off + (size_t)q0 * DH;
    const __half* Kg = g_K + bh_off;
    const __half* Vg = g_V + bh_off;
    const __half* mrow = g_Mc + (size_t)b * SEQ;

    auto load_tile = [&](int i, int buf) {
        const int k0 = i * 64;
        const __half* srcs[2] = { Kg + (size_t)k0 * DH, Vg + (size_t)k0 * DH };
        #pragma unroll
        for (int p = 0; p < 2; ++p) {
            const uint32_t base = sbase + ATT_Q + buf * ATT_BUF + p * ATT_PART;
            #pragma unroll
            for (int it = 0; it < 4; ++it) {
                int idx = tid + it * ATT_THR;
                int row = idx >> 3;
                int seg = idx & 7;
                cpa16(base + (uint32_t)row * (ATT_LDS * 2) + seg * 16,
                      srcs[p] + (size_t)row * DH + seg * 8);
            }
        }
        if (tid < 8)
            cpa16(sbase + ATT_MASK + buf * 128 + tid * 16, mrow + k0 + tid * 8);
        CPA_COMMIT();
    };

    {   // ones-column (V cols 64-71) for both buffers
        int bufi = tid >> 6;
        int row  = tid & 63;
        uint4* p = (uint4*)(sm + ATT_Q + bufi * ATT_BUF + ATT_PART
                            + row * (ATT_LDS * 2) + 128);
        *p = make_uint4(0x00003C00u, 0u, 0u, 0u);
    }

    {   // stage Q (128 rows)
        #pragma unroll
        for (int it = 0; it < 8; ++it) {
            int idx = tid + it * ATT_THR;
            int row = idx >> 3;
            int seg = idx & 7;
            cpa16(sbase + SWZ((uint32_t)row * 128 + seg * 16),
                  Qg + (size_t)row * DH + seg * 8);
        }
        CPA_COMMIT();
    }
    load_tile(0, 0);
    CPA_WAIT(0);
    __syncthreads();

    uint32_t qf[2][4][4];
    #pragma unroll
    for (int t = 0; t < 4; ++t)
        #pragma unroll
        for (int mf = 0; mf < 2; mf++) {
            const int row = wid * 32 + mf * 16 + (lane & 15);
            const uint32_t colb = (uint32_t)(t * 16 + ((lane & 16) ? 8 : 0)) * 2;
            ldsm4(qf[mf][t], sbase + SWZ((uint32_t)row * 128 + colb));
        }

    uint32_t eones[2];
    {
        const int krow = lane & 15;
        ldsm2t(eones, sbase + ATT_Q + ATT_PART + (uint32_t)krow * (ATT_LDS * 2) + 128);
    }

    float o[2][8][4];
    float oE[2][4];
    #pragma unroll
    for (int mf = 0; mf < 2; mf++) {
        #pragma unroll
        for (int j = 0; j < 8; j++)
            #pragma unroll
            for (int cc = 0; cc < 4; cc++) o[mf][j][cc] = 0.0f;
        #pragma unroll
        for (int cc = 0; cc < 4; cc++) oE[mf][cc] = 0.0f;
    }

    for (int i = 0; i < nkt; ++i) {
        const int buf = i & 1;
        if (i + 1 < nkt) {
            load_tile(i + 1, buf ^ 1);
            CPA_WAIT(1);
        } else {
            CPA_WAIT(0);
        }
        __syncthreads();

        const uint32_t kbase = sbase + ATT_Q + buf * ATT_BUF;

        float s[2][8][4];
        #pragma unroll
        for (int mf = 0; mf < 2; mf++)
            #pragma unroll
            for (int j = 0; j < 8; j++)
                #pragma unroll
                for (int cc = 0; cc < 4; cc++) s[mf][j][cc] = 0.0f;

        #pragma unroll
        for (int t = 0; t < 4; ++t) {
            #pragma unroll
            for (int nf2 = 0; nf2 < 4; ++nf2) {
                const int nrow = nf2 * 16 + (lane & 7) + ((lane & 16) ? 8 : 0);
                const uint32_t colb = (uint32_t)(t * 16 + ((lane & 8) ? 8 : 0)) * 2;
                uint32_t th[4];
                ldsm4(th, kbase + (uint32_t)nrow * (ATT_LDS * 2) + colb);
                const int j = 2 * nf2;
                #pragma unroll
                for (int mf = 0; mf < 2; mf++) {
                    mma_f16(s[mf][j],   qf[mf][t], th[0], th[1]);
                    mma_f16(s[mf][j+1], qf[mf][t], th[2], th[3]);
                }
            }
        }

        uint32_t ph[2][8][2];
        uint32_t mh[8];
        #pragma unroll
        for (int j = 0; j < 8; j++)
            mh[j] = *(const uint32_t*)(sm + ATT_MASK + buf * 128
                                       + (8 * j + 2 * (lane & 3)) * 2);
        #pragma unroll
        for (int mf = 0; mf < 2; mf++)
            #pragma unroll
            for (int j = 0; j < 8; j++) {
                ph[mf][j][0] = hmul2(ex2h2(packh(s[mf][j][0], s[mf][j][1])), mh[j]);
                ph[mf][j][1] = hmul2(ex2h2(packh(s[mf][j][2], s[mf][j][3])), mh[j]);
            }

        #pragma unroll
        for (int t = 0; t < 4; ++t) {
            uint32_t a0[4] = { ph[0][2*t][0], ph[0][2*t][1],
                               ph[0][2*t+1][0], ph[0][2*t+1][1] };
            uint32_t a1[4] = { ph[1][2*t][0], ph[1][2*t][1],
                               ph[1][2*t+1][0], ph[1][2*t+1][1] };
            mma_f16(oE[0], a0, eones[0], eones[1]);
            mma_f16(oE[1], a1, eones[0], eones[1]);
            #pragma unroll
            for (int nf2 = 0; nf2 < 4; ++nf2) {
                const int krow = t * 16 + (lane & 15);
                const uint32_t colb = (uint32_t)(nf2 * 16 + ((lane & 16) ? 8 : 0)) * 2;
                uint32_t tv[4];
                ldsm4t(tv, kbase + ATT_PART + (uint32_t)krow * (ATT_LDS * 2) + colb);
                const int j = 2 * nf2;
                mma_f16(o[0][j],   a0, tv[0], tv[1]);
                mma_f16(o[0][j+1], a0, tv[2], tv[3]);
                mma_f16(o[1][j],   a1, tv[0], tv[1]);
                mma_f16(o[1][j+1], a1, tv[2], tv[3]);
            }
        }
        __syncthreads();
    }

    #pragma unroll
    for (int mf = 0; mf < 2; mf++) {
        const float l0 = __shfl_sync(0xffffffffu, oE[mf][0], lane & ~3);
        const float l1 = __shfl_sync(0xffffffffu, oE[mf][2], lane & ~3);
        const float inv0 = 1.0f / l0;
        const float inv1 = 1.0f / l1;
        const int r0 = q0 + wid * 32 + mf * 16 + (lane >> 2);
        #pragma unroll
        for (int j = 0; j < 8; j++) {
            const int col = h * 64 + 8 * j + 2 * (lane & 3);
            #pragma unroll
            for (int half = 0; half < 2; half++) {
                const int gr = r0 + half * 8;
                const float inv = half ? inv1 : inv0;
                float v0 = o[mf][j][half*2]     * inv;
                float v1 = o[mf][j][half*2 + 1] * inv;
                size_t off = (size_t)(b * SEQ + gr) * HID + col;
                *(uint32_t*)(g_O + off) = packh(v0, v1);
            }
        }
    }
}

// ---------------- fused mega kernel: KV | Q | attn | out --------------------
// bid order guarantees deps point to smaller bids (dispatch is bid-monotone).
__global__ __launch_bounds__(128, 2)
void mega(const float* __restrict__ bq, const float* __restrict__ bk,
          const float* __restrict__ bv, const float* __restrict__ bo,
          float* __restrict__ out)
{
    const int bid = blockIdx.x;
    const int tid = threadIdx.x;

    if (bid < 512) {                       // ---- K/V projections ----
        const int z   = bid >> 8;          // 0=K, 1=V
        const int r   = bid & 255;
        const int b   = r >> 7;
        const int rem = r & 127;
        const int my  = rem >> 3;          // m-tile 0..15
        const int x   = rem & 7;
        const int cnt = g_Cnt[b];
        const int pad = (cnt + 127) & ~127;
        if (my * 128 < pad) {
            __half* Ch = (z ? g_V : g_K) + (size_t)b * HEADS * SEQ * DH;
            hmma_gemm(g_X + (size_t)b * SEQ * HID,
                      g_Wt + (size_t)(z + 1) * HID * HID,
                      z ? bv : bk, 1.0f, nullptr, Ch, 2,
                      my * 128, x * 128, g_Idx + b * SEQ, cnt);
        }
        __syncthreads();
        __threadfence();
        if (tid == 0) atomicAdd(&g_CntKV[b], 1);
    } else if (bid < 768) {                // ---- Q projection ----
        const int r = bid - 512;
        hmma_gemm(g_X, g_Wt, bq, SCALE_L2, nullptr, g_Q, 1,
                  (r >> 3) * 128, (r & 7) * 128, nullptr, 0);
        __syncthreads();
        __threadfence();
        if (tid == 0) atomicExch(&g_FlagQ[r], 1);
    } else if (bid < 1280) {               // ---- attention ----
        const int r  = bid - 768;
        const int b  = r >> 8;
        const int h  = (r >> 4) & 15;
        const int qx = r & 15;
        if (tid == 0) {
            spin_ge(&g_FlagQ[(b * 16 + qx) * 8 + (h >> 1)], 1);
            spin_ge(&g_CntKV[b], 256);
        }
        __syncthreads();
        attn_body(b, h, qx * 128);
        __syncthreads();
        __threadfence();
        if (tid == 0) atomicAdd(&g_CntO[b * 16 + qx], 1);
    } else {                               // ---- output projection ----
        const int r = bid - 1280;
        const int y = r >> 3;
        if (tid == 0) spin_ge(&g_CntO[y], 16);
        __syncthreads();
        hmma_gemm(g_O, g_Wt + (size_t)3 * HID * HID, bo, 1.0f, out, nullptr, 0,
                  y * 128, (r & 7) * 128, nullptr, 0);
    }
}

// ---------------------------------------------------------------------------
extern "C" void kernel_launch(void* const* d_in, const int* in_sizes, int n_in,
                              void* d_out, int out_size)
{
    (void)in_sizes; (void)n_in; (void)out_size;
    const float* x    = (const float*)d_in[0];
    const float* mask = (const float*)d_in[1];
    const float* Wq   = (const float*)d_in[2];
    const float* bq   = (const float*)d_in[3];
    const float* Wk   = (const float*)d_in[4];
    const float* bk   = (const float*)d_in[5];
    const float* Wv   = (const float*)d_in[6];
    const float* bv   = (const float*)d_in[7];
    const float* Wo   = (const float*)d_in[8];
    const float* bo   = (const float*)d_in[9];
    float* out = (float*)d_out;

    __half* xh;
    cudaGetSymbolAddress((void**)&xh, g_X);

    // 0) pre-passes (compact also resets dependency flags)
    const int n4 = MROWS * HID / 4;
    xconv_kernel<<<(n4 + 255) / 256, 256>>>(x, xh, n4);
    compact_kernel<<<BATCH, 256>>>(mask);
    wconv_kernel<<<dim3(32, 32, 4), dim3(32, 8)>>>(Wq, Wk, Wv, Wo);

    // 1) fused KV + Q + attention + output with flag-based dependencies
    cudaFuncSetAttribute(mega, cudaFuncAttributeMaxDynamicSharedMemorySize, GEMM_SMEM);
    mega<<<1536, 128, GEMM_SMEM>>>(bq, bk, bv, bo, out);
}